// round 15
// baseline (speedup 1.0000x reference)
#include <cuda_runtime.h>
#include <cuda_bf16.h>
#include <cstdint>
#include <cstring>
#include <math.h>

#define Bsz 8
#define HWsz 16384
#define Cch 128
#define Ntot (Bsz*HWsz)
#define NCHUNK 32         // qk split-K chunks per batch
typedef __nv_bfloat16 bf16;

// ---------------- scratch (device globals; no allocation) ----------------
__device__ bf16  g_q2[(size_t)Ntot*Cch];
__device__ bf16  g_kv2[(size_t)Ntot*2*Cch];
__device__ float g_att_part[(size_t)Bsz*NCHUNK*Cch*Cch];
__device__ float g_att[(size_t)Bsz*Cch*Cch];
__device__ float g_norm_part[2*Bsz*16*Cch];
__device__ bf16  g_W2h[Bsz*Cch*Cch];

// ---------------- mma / ldmatrix / cp.async helpers ----------------
__device__ __forceinline__ unsigned sptr(const void* p) {
    return (unsigned)__cvta_generic_to_shared(p);
}
__device__ __forceinline__ void ldm_x4(unsigned* r, unsigned a) {
    asm volatile("ldmatrix.sync.aligned.m8n8.x4.shared.b16 {%0,%1,%2,%3}, [%4];"
        : "=r"(r[0]), "=r"(r[1]), "=r"(r[2]), "=r"(r[3]) : "r"(a));
}
__device__ __forceinline__ void ldm_x4_t(unsigned* r, unsigned a) {
    asm volatile("ldmatrix.sync.aligned.m8n8.x4.trans.shared.b16 {%0,%1,%2,%3}, [%4];"
        : "=r"(r[0]), "=r"(r[1]), "=r"(r[2]), "=r"(r[3]) : "r"(a));
}
__device__ __forceinline__ void ldm_x2(unsigned* r, unsigned a) {
    asm volatile("ldmatrix.sync.aligned.m8n8.x2.shared.b16 {%0,%1}, [%2];"
        : "=r"(r[0]), "=r"(r[1]) : "r"(a));
}
__device__ __forceinline__ void ldm_x2_t(unsigned* r, unsigned a) {
    asm volatile("ldmatrix.sync.aligned.m8n8.x2.trans.shared.b16 {%0,%1}, [%2];"
        : "=r"(r[0]), "=r"(r[1]) : "r"(a));
}
__device__ __forceinline__ void mma16816(float* c, const unsigned* a, const unsigned* b) {
    asm volatile("mma.sync.aligned.m16n8k16.row.col.f32.bf16.bf16.f32 "
        "{%0,%1,%2,%3},{%4,%5,%6,%7},{%8,%9},{%0,%1,%2,%3};"
        : "+f"(c[0]), "+f"(c[1]), "+f"(c[2]), "+f"(c[3])
        : "r"(a[0]), "r"(a[1]), "r"(a[2]), "r"(a[3]), "r"(b[0]), "r"(b[1]));
}
__device__ __forceinline__ void pf_l2(const void* p) {
    asm volatile("prefetch.global.L2 [%0];" :: "l"(p));
}
__device__ __forceinline__ void cp_async16(unsigned dst, const void* src) {
    asm volatile("cp.async.cg.shared.global [%0], [%1], 16;" :: "r"(dst), "l"(src));
}
#define CP_COMMIT() asm volatile("cp.async.commit_group;" ::: "memory")
#define CP_WAIT0()  asm volatile("cp.async.wait_group 0;" ::: "memory")

#define SROW 136          // ldmatrix-padded stride (halves)
#define RROW 132          // ring row stride (halves)
#define SLOTH (128*RROW)  // ring slot size in halves

// ================= MEGAFUSE: LN + 1x1 GEMM + dwconv3x3 + sumsq =================
// grid (3 paths, 16 strips, Bsz), 512 threads.
__global__ __launch_bounds__(512)
void megafuse(const float* __restrict__ cur, const float* __restrict__ pre,
              const float* __restrict__ ln1w, const float* __restrict__ ln1b,
              const float* __restrict__ ln2w, const float* __restrict__ ln2b,
              const float* __restrict__ qw1, const float* __restrict__ kvw1,
              const float* __restrict__ qb1, const float* __restrict__ kvb1,
              const float* __restrict__ qw2, const float* __restrict__ qb2,
              const float* __restrict__ kvw2, const float* __restrict__ kvb2)
{
    extern __shared__ bf16 sm[];
    bf16* As   = sm;                    // [128][SROW]
    bf16* Ws   = sm + 128 * SROW;       // [128][SROW]
    bf16* ring = sm + 2 * 128 * SROW;   // 3 x [128][RROW]
    __shared__ float2 red2[512];

    int tid = threadIdx.x, lane = tid & 31, w = tid >> 5;
    int path = blockIdx.x, strip = blockIdx.y, b = blockIdx.z;
    int y0 = strip * 8;

    const float* Ain; const float* lnw; const float* lnb; const float* Wf;
    const float* gb; const float* cwt; const float* cb;
    bf16* outp; int ldout, coloff, which, dosq;
    if (path == 0) {
        Ain = cur; lnw = ln2w; lnb = ln2b; Wf = qw1;
        gb = qb1; cwt = qw2; cb = qb2;
        outp = g_q2; ldout = 128; coloff = 0; which = 0; dosq = 1;
    } else if (path == 1) {
        Ain = pre; lnw = ln1w; lnb = ln1b; Wf = kvw1;
        gb = kvb1; cwt = kvw2; cb = kvb2;
        outp = g_kv2; ldout = 256; coloff = 0; which = 1; dosq = 1;
    } else {
        Ain = pre; lnw = ln1w; lnb = ln1b; Wf = kvw1 + 128 * 128;
        gb = kvb1 + 128; cwt = kvw2 + 128 * 9; cb = kvb2 + 128;
        outp = g_kv2; ldout = 256; coloff = 128; which = 0; dosq = 0;
    }

    for (int it = tid; it < 128 * 16; it += 512) {
        int o = it >> 4, c8 = (it & 15) * 8;
        const float* wp = Wf + (size_t)o * 128 + c8;
        float4 f0 = *(const float4*)wp;
        float4 f1 = *(const float4*)(wp + 4);
        bf16* dp = Ws + o * SROW + c8;
        *(__nv_bfloat162*)(dp)     = __floats2bfloat162_rn(f0.x, f0.y);
        *(__nv_bfloat162*)(dp + 2) = __floats2bfloat162_rn(f0.z, f0.w);
        *(__nv_bfloat162*)(dp + 4) = __floats2bfloat162_rn(f1.x, f1.y);
        *(__nv_bfloat162*)(dp + 6) = __floats2bfloat162_rn(f1.z, f1.w);
    }

    int cp = tid & 63, xg = tid >> 6;
    int cg = cp * 2;
    __nv_bfloat162 cw[9];
    #pragma unroll
    for (int t = 0; t < 9; t++)
        cw[t] = __floats2bfloat162_rn(cwt[cg * 9 + t], cwt[cg * 9 + 9 + t]);
    __nv_bfloat162 cb2 = __floats2bfloat162_rn(cb[cg], cb[cg + 1]);
    const __nv_bfloat162 zz = __floats2bfloat162_rn(0.f, 0.f);

    float4 wv = *(const float4*)(lnw + lane * 4);
    float4 bv = *(const float4*)(lnb + lane * 4);

    int wm = (w & 3) * 32, wn = (w >> 2) * 32;
    int arow  = (lane & 7) + ((lane >> 3) & 1) * 8;
    int akoff = (lane >> 4) * 8;
    int brow  = (lane & 7);
    int bkoff = ((lane >> 3) & 1) * 8;
    int g = lane >> 2, t2 = (lane & 3) * 2;

    float sq0 = 0.f, sq1 = 0.f;

    {
        int r = y0 - 1;
        if ((unsigned)r < 128u) {
            #pragma unroll
            for (int i = 0; i < 8; i++) {
                int p = w * 8 + i;
                pf_l2(Ain + ((size_t)b * HWsz + (size_t)r * 128 + p) * 128 + lane * 4);
            }
        }
    }

    for (int ri = 0; ri < 10; ri++) {
        int r = y0 - 1 + ri;
        bf16* rs = ring + (ri % 3) * SLOTH;

        if ((unsigned)r < 128u) {
            #pragma unroll
            for (int i = 0; i < 8; i++) {
                int p = w * 8 + i;
                const float* ap = Ain + ((size_t)b * HWsz + (size_t)r * 128 + p) * 128 + lane * 4;
                float4 v = *(const float4*)ap;
                float s  = v.x + v.y + v.z + v.w;
                float ss = fmaf(v.x, v.x, fmaf(v.y, v.y, fmaf(v.z, v.z, v.w * v.w)));
                #pragma unroll
                for (int o = 16; o; o >>= 1) {
                    s  += __shfl_xor_sync(0xFFFFFFFFu, s,  o);
                    ss += __shfl_xor_sync(0xFFFFFFFFu, ss, o);
                }
                float mu  = s * (1.0f / 128.0f);
                float inv = rsqrtf(ss * (1.0f / 128.0f) - mu * mu + 1e-5f);
                float x0 = (v.x - mu) * inv * wv.x + bv.x;
                float x1 = (v.y - mu) * inv * wv.y + bv.y;
                float x2 = (v.z - mu) * inv * wv.z + bv.z;
                float x3 = (v.w - mu) * inv * wv.w + bv.w;
                *(__nv_bfloat162*)(As + p * SROW + lane * 4)     = __floats2bfloat162_rn(x0, x1);
                *(__nv_bfloat162*)(As + p * SROW + lane * 4 + 2) = __floats2bfloat162_rn(x2, x3);
            }
            __syncthreads();

            {
                int rn = r + 1;
                if (ri + 1 < 10 && (unsigned)rn < 128u) {
                    #pragma unroll
                    for (int i = 0; i < 8; i++) {
                        int p = w * 8 + i;
                        pf_l2(Ain + ((size_t)b * HWsz + (size_t)rn * 128 + p) * 128 + lane * 4);
                    }
                }
            }

            float acc[2][4][4];
            #pragma unroll
            for (int mi = 0; mi < 2; mi++)
                #pragma unroll
                for (int ni = 0; ni < 4; ni++)
                    #pragma unroll
                    for (int t = 0; t < 4; t++) acc[mi][ni][t] = 0.f;

            #pragma unroll
            for (int k0 = 0; k0 < 128; k0 += 16) {
                unsigned af[2][4];
                unsigned bfr[4][2];
                #pragma unroll
                for (int mi = 0; mi < 2; mi++)
                    ldm_x4(af[mi], sptr(As + (wm + 16 * mi + arow) * SROW + k0 + akoff));
                #pragma unroll
                for (int ni = 0; ni < 4; ni++)
                    ldm_x2(bfr[ni], sptr(Ws + (wn + 8 * ni + brow) * SROW + k0 + bkoff));
                #pragma unroll
                for (int mi = 0; mi < 2; mi++)
                    #pragma unroll
                    for (int ni = 0; ni < 4; ni++)
                        mma16816(acc[mi][ni], af[mi], bfr[ni]);
            }

            #pragma unroll
            for (int mi = 0; mi < 2; mi++) {
                int p0 = wm + 16 * mi + g;
                #pragma unroll
                for (int ni = 0; ni < 4; ni++) {
                    int col = wn + 8 * ni + t2;
                    float2 bb = *(const float2*)(gb + col);
                    *(__nv_bfloat162*)(rs + p0 * RROW + col) =
                        __floats2bfloat162_rn(acc[mi][ni][0] + bb.x, acc[mi][ni][1] + bb.y);
                    *(__nv_bfloat162*)(rs + (p0 + 8) * RROW + col) =
                        __floats2bfloat162_rn(acc[mi][ni][2] + bb.x, acc[mi][ni][3] + bb.y);
                }
            }
            __syncthreads();
        } else {
            __syncthreads();
            for (int it = tid; it < 128 * (RROW / 2); it += 512)
                ((unsigned*)rs)[it] = 0u;
            __syncthreads();
        }

        if (ri >= 2) {
            const __nv_bfloat162* r0 = (const __nv_bfloat162*)(ring + ((ri - 2) % 3) * SLOTH);
            const __nv_bfloat162* r1 = (const __nv_bfloat162*)(ring + ((ri - 1) % 3) * SLOTH);
            const __nv_bfloat162* r2 = (const __nv_bfloat162*)(ring + (ri % 3) * SLOTH);
            int yo = y0 + ri - 2;
            int x0 = xg * 16;
            const int RW = RROW / 2;

            __nv_bfloat162 m0, m1, m2, c0, c1, c2;
            if (x0 > 0) {
                m0 = r0[(x0 - 1) * RW + cp]; m1 = r1[(x0 - 1) * RW + cp]; m2 = r2[(x0 - 1) * RW + cp];
            } else { m0 = zz; m1 = zz; m2 = zz; }
            c0 = r0[x0 * RW + cp]; c1 = r1[x0 * RW + cp]; c2 = r2[x0 * RW + cp];

            bf16* ob = outp + ((size_t)b * HWsz + (size_t)yo * 128) * ldout + coloff + cg;
            #pragma unroll 4
            for (int xi = 0; xi < 16; xi++) {
                int x = x0 + xi;
                __nv_bfloat162 p0, p1, p2;
                if (x < 127) {
                    p0 = r0[(x + 1) * RW + cp]; p1 = r1[(x + 1) * RW + cp]; p2 = r2[(x + 1) * RW + cp];
                } else { p0 = zz; p1 = zz; p2 = zz; }
                __nv_bfloat162 a = cb2;
                a = __hfma2(m0, cw[0], a); a = __hfma2(c0, cw[1], a); a = __hfma2(p0, cw[2], a);
                a = __hfma2(m1, cw[3], a); a = __hfma2(c1, cw[4], a); a = __hfma2(p1, cw[5], a);
                a = __hfma2(m2, cw[6], a); a = __hfma2(c2, cw[7], a); a = __hfma2(p2, cw[8], a);
                *(__nv_bfloat162*)(ob + (size_t)x * ldout) = a;
                if (dosq) {
                    float f0 = __bfloat162float(__low2bfloat16(a));
                    float f1 = __bfloat162float(__high2bfloat16(a));
                    sq0 = fmaf(f0, f0, sq0);
                    sq1 = fmaf(f1, f1, sq1);
                }
                m0 = c0; c0 = p0; m1 = c1; c1 = p1; m2 = c2; c2 = p2;
            }
        }
    }

    red2[tid] = make_float2(sq0, sq1);
    __syncthreads();
    if (dosq && tid < 64) {
        float t0 = 0.f, t1 = 0.f;
        #pragma unroll
        for (int xx = 0; xx < 8; xx++) {
            float2 v = red2[xx * 64 + tid];
            t0 += v.x; t1 += v.y;
        }
        float* dst = g_norm_part + ((size_t)(which * 8 + b) * 16 + strip) * 128 + tid * 2;
        dst[0] = t0; dst[1] = t1;
    }
}

// ---------------- QK^T: cp.async double-buffered pipeline ----------------
__global__ __launch_bounds__(256, 2)
void qk_kernel()
{
    __shared__ bf16 Qs[2][32 * SROW];
    __shared__ bf16 Ks[2][32 * SROW];
    int bx = blockIdx.x;
    int b = bx >> 5, chunk = bx & 31;
    const bf16* Qb = g_q2  + (size_t)b * HWsz * 128;
    const bf16* Kb = g_kv2 + (size_t)b * HWsz * 256;
    int tid = threadIdx.x, lane = tid & 31, w = tid >> 5;
    int wm = (w & 1) * 64, wn = (w >> 1) * 32;

    int at_row  = (lane & 7) + ((lane >> 4) & 1) * 8;
    int at_coff = ((lane >> 3) & 1) * 8;
    int bt_row  = (lane & 7) + ((lane >> 3) & 1) * 8;
    int g = lane >> 2, t2 = (lane & 3) * 2;

    int r0s = tid >> 4,         c0s = (tid & 15) * 8;
    int r1s = (tid + 256) >> 4, c1s = ((tid + 256) & 15) * 8;

    float acc[4][4][4];
    #pragma unroll
    for (int mi = 0; mi < 4; mi++)
        #pragma unroll
        for (int ni = 0; ni < 4; ni++)
            #pragma unroll
            for (int t = 0; t < 4; t++) acc[mi][ni][t] = 0.f;

    const int NS = 16;
    int nbase = chunk * 512;

    cp_async16(sptr(&Qs[0][r0s * SROW + c0s]), Qb + (size_t)(nbase + r0s) * 128 + c0s);
    cp_async16(sptr(&Qs[0][r1s * SROW + c1s]), Qb + (size_t)(nbase + r1s) * 128 + c1s);
    cp_async16(sptr(&Ks[0][r0s * SROW + c0s]), Kb + (size_t)(nbase + r0s) * 256 + c0s);
    cp_async16(sptr(&Ks[0][r1s * SROW + c1s]), Kb + (size_t)(nbase + r1s) * 256 + c1s);
    CP_COMMIT();

    for (int st = 0; st < NS; st++) {
        CP_WAIT0();
        __syncthreads();

        if (st + 1 < NS) {
            int n0 = nbase + (st + 1) * 32;
            int bb = (st + 1) & 1;
            cp_async16(sptr(&Qs[bb][r0s * SROW + c0s]), Qb + (size_t)(n0 + r0s) * 128 + c0s);
            cp_async16(sptr(&Qs[bb][r1s * SROW + c1s]), Qb + (size_t)(n0 + r1s) * 128 + c1s);
            cp_async16(sptr(&Ks[bb][r0s * SROW + c0s]), Kb + (size_t)(n0 + r0s) * 256 + c0s);
            cp_async16(sptr(&Ks[bb][r1s * SROW + c1s]), Kb + (size_t)(n0 + r1s) * 256 + c1s);
            CP_COMMIT();
        }

        const bf16* Qc = Qs[st & 1];
        const bf16* Kc = Ks[st & 1];
        #pragma unroll
        for (int k0 = 0; k0 < 32; k0 += 16) {
            unsigned af[4][4];
            unsigned bfr[4][2];
            #pragma unroll
            for (int mi = 0; mi < 4; mi++)
                ldm_x4_t(af[mi], sptr(Qc + (k0 + at_row) * SROW + wm + 16 * mi + at_coff));
            #pragma unroll
            for (int ni = 0; ni < 4; ni++)
                ldm_x2_t(bfr[ni], sptr(Kc + (k0 + bt_row) * SROW + wn + 8 * ni));
            #pragma unroll
            for (int mi = 0; mi < 4; mi++)
                #pragma unroll
                for (int ni = 0; ni < 4; ni++)
                    mma16816(acc[mi][ni], af[mi], bfr[ni]);
        }
    }

    float* P = g_att_part + (size_t)bx * 16384;
    #pragma unroll
    for (int mi = 0; mi < 4; mi++) {
        int row = wm + 16 * mi + g;
        #pragma unroll
        for (int ni = 0; ni < 4; ni++) {
            int col = wn + 8 * ni + t2;
            *(float2*)(P + row * 128 + col)       = make_float2(acc[mi][ni][0], acc[mi][ni][1]);
            *(float2*)(P + (row + 8) * 128 + col) = make_float2(acc[mi][ni][2], acc[mi][ni][3]);
        }
    }
}

// ---------------- softmax: one block per (b,c), thread = d ----------------
__global__ __launch_bounds__(128)
void softmax_kernel()
{
    __shared__ float rbuf[8];
    int bc = blockIdx.x;
    int b = bc >> 7, c = bc & 127;
    int d = threadIdx.x;

    float sq = 0.f, sk = 0.f;
    #pragma unroll
    for (int t = 0; t < 16; t++) {
        sq += g_norm_part[((size_t)b * 16 + t) * 128 + c];
        sk += g_norm_part[((size_t)(8 + b) * 16 + t) * 128 + d];
    }
    float invq = 1.0f / fmaxf(sqrtf(sq), 1e-12f);
    float invk = 1.0f / fmaxf(sqrtf(sk), 1e-12f);

    const float* P = g_att_part + ((size_t)b * NCHUNK * 128 + c) * 128 + d;
    float s = 0.f;
    #pragma unroll 8
    for (int ch = 0; ch < NCHUNK; ch++)
        s += P[(size_t)ch * 16384];

    float l = s * invq * invk;

    float mx = l;
    #pragma unroll
    for (int o = 16; o; o >>= 1) mx = fmaxf(mx, __shfl_xor_sync(0xFFFFFFFFu, mx, o));
    if ((d & 31) == 0) rbuf[d >> 5] = mx;
    __syncthreads();
    mx = fmaxf(fmaxf(rbuf[0], rbuf[1]), fmaxf(rbuf[2], rbuf[3]));

    float e = expf(l - mx);
    float sum = e;
    #pragma unroll
    for (int o = 16; o; o >>= 1) sum += __shfl_xor_sync(0xFFFFFFFFu, sum, o);
    __syncthreads();
    if ((d & 31) == 0) rbuf[4 + (d >> 5)] = sum;
    __syncthreads();
    sum = (rbuf[4] + rbuf[5]) + (rbuf[6] + rbuf[7]);

    g_att[(size_t)bc * 128 + d] = e / sum;
}

// ---------------- W2[b] = out_w @ att[b]: grid (Bsz, 16), 1024 thr, 8-way e-split ----------------
__global__ __launch_bounds__(1024)
void w2_kernel(const float* __restrict__ out_w)
{
    __shared__ float sw[8 * 128];
    __shared__ float red[8 * 8 * 128];
    int b = blockIdx.x, ct = blockIdx.y;
    int tid = threadIdx.x;
    int d = tid & 127, eh = tid >> 7;

    for (int it = tid; it < 8 * 128; it += 1024)
        sw[it] = out_w[(size_t)(ct * 8 + (it >> 7)) * 128 + (it & 127)];
    __syncthreads();

    float acc[8];
    #pragma unroll
    for (int ci = 0; ci < 8; ci++) acc[ci] = 0.f;

    const float* A = g_att + (size_t)b * 16384 + d;
    int e0 = eh * 16;
    #pragma unroll 8
    for (int ei = 0; ei < 16; ei++) {
        int e = e0 + ei;
        float a = A[(size_t)e * 128];
        #pragma unroll
        for (int ci = 0; ci < 8; ci++)
            acc[ci] = fmaf(sw[ci * 128 + e], a, acc[ci]);
    }

    #pragma unroll
    for (int ci = 0; ci < 8; ci++)
        red[(eh * 8 + ci) * 128 + d] = acc[ci];
    __syncthreads();

    {
        int idx = tid;
        int ci = idx >> 7, d2 = idx & 127;
        float v = 0.f;
        #pragma unroll
        for (int e8 = 0; e8 < 8; e8++)
            v += red[(e8 * 8 + ci) * 128 + d2];
        g_W2h[(size_t)b * 16384 + (size_t)(ct * 8 + ci) * 128 + d2] = __float2bfloat16_rn(v);
    }
}

// ---------------- final: out[b,n,c] = sum_d W2[c,d] v[b,n,d] + out_b[c] + cur ----------------
__global__ __launch_bounds__(256, 2)
void vgemm(const float* __restrict__ cur, const float* __restrict__ out_b,
           float* __restrict__ out)
{
    extern __shared__ bf16 sm[];
    bf16* As = sm;
    bf16* Bs = sm + 128 * SROW;
    int b = blockIdx.z;
    int m0 = blockIdx.y * 128;
    const bf16* V  = g_kv2 + (size_t)b * HWsz * 256 + 128;
    const bf16* W2 = g_W2h + (size_t)b * 16384;
    int tid = threadIdx.x, lane = tid & 31, w = tid >> 5;

    // prefetch this block's cur tile (128 rows x 512B) into L2
    const float* curb = cur + (size_t)b * HWsz * 128;
    #pragma unroll
    for (int t = 0; t < 2; t++)
        pf_l2(curb + (size_t)m0 * 128 + (size_t)(tid + t * 256) * 128);

    for (int it = tid; it < 128 * 16; it += 256) {
        int r = it >> 4, c8 = (it & 15) * 8;
        *(uint4*)(As + r * SROW + c8) = *(const uint4*)(V + (size_t)(m0 + r) * 256 + c8);
        *(uint4*)(Bs + r * SROW + c8) = *(const uint4*)(W2 + (size_t)r * 128 + c8);
    }
    __syncthreads();

    int wm = (w & 1) * 64, wn = (w >> 1) * 32;
    int arow  = (lane & 7) + ((lane >> 3) & 1) * 8;
    int akoff = (lane >> 4) * 8;
    int brow  = (lane & 7);
    int bkoff = ((lane >> 3) & 1) * 8;
    int g = lane >> 2, t2 = (lane & 3) * 2;

    float acc[4][4][4];
    #pragma unroll
    for (int mi = 0; mi < 4; mi++)
        #pragma unroll
        for (int ni = 0; ni < 4; ni++)
            #pragma unroll
            for (int t = 0; t < 4; t++) acc[mi][ni][t] = 0.f;

    for (int k0 = 0; k0 < 128; k0 += 16) {
        unsigned af[4][4];
        unsigned bfr[4][2];
        #pragma unroll
        for (int mi = 0; mi < 4; mi++)
            ldm_x4(af[mi], sptr(As + (wm + 16 * mi + arow) * SROW + k0 + akoff));
        #pragma unroll
        for (int ni = 0; ni < 4; ni++)
            ldm_x2(bfr[ni], sptr(Bs + (wn + 8 * ni + brow) * SROW + k0 + bkoff));
        #pragma unroll
        for (int mi = 0; mi < 4; mi++)
            #pragma unroll
            for (int ni = 0; ni < 4; ni++)
                mma16816(acc[mi][ni], af[mi], bfr[ni]);
    }

    float* outb = out + (size_t)b * HWsz * 128;
    #pragma unroll
    for (int mi = 0; mi < 4; mi++) {
        int r0 = m0 + wm + 16 * mi + g;
        #pragma unroll
        for (int ni = 0; ni < 4; ni++) {
            int col = wn + 8 * ni + t2;
            float2 bb = *(const float2*)(out_b + col);
            float2 c0 = *(const float2*)(curb + (size_t)r0 * 128 + col);
            float2 c1 = *(const float2*)(curb + (size_t)(r0 + 8) * 128 + col);
            *(float2*)(outb + (size_t)r0 * 128 + col) =
                make_float2(acc[mi][ni][0] + bb.x + c0.x, acc[mi][ni][1] + bb.y + c0.y);
            *(float2*)(outb + (size_t)(r0 + 8) * 128 + col) =
                make_float2(acc[mi][ni][2] + bb.x + c1.x, acc[mi][ni][3] + bb.y + c1.y);
        }
    }
}

// ---------------- host ----------------
extern "C" void kernel_launch(void* const* d_in, const int* in_sizes, int n_in,
                              void* d_out, int out_size)
{
    const float* pre   = (const float*)d_in[0];
    const float* cur   = (const float*)d_in[1];
    const float* ln1_w = (const float*)d_in[2];
    const float* ln1_b = (const float*)d_in[3];
    const float* ln2_w = (const float*)d_in[4];
    const float* ln2_b = (const float*)d_in[5];
    const float* q_w1  = (const float*)d_in[6];
    const float* q_b1  = (const float*)d_in[7];
    const float* q_w2  = (const float*)d_in[8];
    const float* q_b2  = (const float*)d_in[9];
    const float* kv_w1 = (const float*)d_in[10];
    const float* kv_b1 = (const float*)d_in[11];
    const float* kv_w2 = (const float*)d_in[12];
    const float* kv_b2 = (const float*)d_in[13];
    const float* out_w = (const float*)d_in[14];
    const float* out_b = (const float*)d_in[15];
    float* out = (float*)d_out;

    const int SMEM_GEMM = 2 * 128 * SROW * (int)sizeof(bf16);                // 69632
    const int SMEM_MF   = (2 * 128 * SROW + 3 * SLOTH) * (int)sizeof(bf16);  // 171008
    cudaFuncSetAttribute(megafuse, cudaFuncAttributeMaxDynamicSharedMemorySize, SMEM_MF);
    cudaFuncSetAttribute(vgemm,    cudaFuncAttributeMaxDynamicSharedMemorySize, SMEM_GEMM);

    megafuse<<<dim3(3, 16, Bsz), 512, SMEM_MF>>>(cur, pre, ln1_w, ln1_b, ln2_w, ln2_b,
                                                 q_w1, kv_w1, q_b1, kv_b1,
                                                 q_w2, q_b2, kv_w2, kv_b2);

    qk_kernel<<<Bsz * NCHUNK, 256>>>();

    softmax_kernel<<<Bsz * 128, 128>>>();

    w2_kernel<<<dim3(Bsz, 16), 1024>>>(out_w);

    vgemm<<<dim3(1, HWsz / 128, Bsz), 256, SMEM_GEMM>>>(cur, out_b, out);

    (void)in_sizes; (void)n_in; (void)out_size;
}

// round 16
// speedup vs baseline: 1.0211x; 1.0211x over previous
#include <cuda_runtime.h>
#include <cuda_bf16.h>
#include <cstdint>
#include <cstring>
#include <math.h>

#define Bsz 8
#define HWsz 16384
#define Cch 128
#define Ntot (Bsz*HWsz)
#define NCHUNK 32         // qk split-K chunks per batch
typedef __nv_bfloat16 bf16;

// ---------------- scratch (device globals; no allocation) ----------------
__device__ bf16  g_q2[(size_t)Ntot*Cch];
__device__ bf16  g_kv2[(size_t)Ntot*2*Cch];
__device__ float g_att_part[(size_t)Bsz*NCHUNK*Cch*Cch];
__device__ float g_att[(size_t)Bsz*Cch*Cch];
__device__ float g_norm_part[2*Bsz*16*Cch];
__device__ bf16  g_W2h[Bsz*Cch*Cch];

// ---------------- mma / ldmatrix / cp.async helpers ----------------
__device__ __forceinline__ unsigned sptr(const void* p) {
    return (unsigned)__cvta_generic_to_shared(p);
}
__device__ __forceinline__ void ldm_x4(unsigned* r, unsigned a) {
    asm volatile("ldmatrix.sync.aligned.m8n8.x4.shared.b16 {%0,%1,%2,%3}, [%4];"
        : "=r"(r[0]), "=r"(r[1]), "=r"(r[2]), "=r"(r[3]) : "r"(a));
}
__device__ __forceinline__ void ldm_x4_t(unsigned* r, unsigned a) {
    asm volatile("ldmatrix.sync.aligned.m8n8.x4.trans.shared.b16 {%0,%1,%2,%3}, [%4];"
        : "=r"(r[0]), "=r"(r[1]), "=r"(r[2]), "=r"(r[3]) : "r"(a));
}
__device__ __forceinline__ void ldm_x2(unsigned* r, unsigned a) {
    asm volatile("ldmatrix.sync.aligned.m8n8.x2.shared.b16 {%0,%1}, [%2];"
        : "=r"(r[0]), "=r"(r[1]) : "r"(a));
}
__device__ __forceinline__ void ldm_x2_t(unsigned* r, unsigned a) {
    asm volatile("ldmatrix.sync.aligned.m8n8.x2.trans.shared.b16 {%0,%1}, [%2];"
        : "=r"(r[0]), "=r"(r[1]) : "r"(a));
}
__device__ __forceinline__ void mma16816(float* c, const unsigned* a, const unsigned* b) {
    asm volatile("mma.sync.aligned.m16n8k16.row.col.f32.bf16.bf16.f32 "
        "{%0,%1,%2,%3},{%4,%5,%6,%7},{%8,%9},{%0,%1,%2,%3};"
        : "+f"(c[0]), "+f"(c[1]), "+f"(c[2]), "+f"(c[3])
        : "r"(a[0]), "r"(a[1]), "r"(a[2]), "r"(a[3]), "r"(b[0]), "r"(b[1]));
}
__device__ __forceinline__ void pf_l2(const void* p) {
    asm volatile("prefetch.global.L2 [%0];" :: "l"(p));
}
__device__ __forceinline__ void cp_async16(unsigned dst, const void* src) {
    asm volatile("cp.async.cg.shared.global [%0], [%1], 16;" :: "r"(dst), "l"(src));
}
#define CP_COMMIT() asm volatile("cp.async.commit_group;" ::: "memory")
#define CP_WAIT0()  asm volatile("cp.async.wait_group 0;" ::: "memory")

#define SROW 136          // ldmatrix-padded stride (halves)
#define RROW 132          // ring row stride (halves)
#define SLOTH (128*RROW)  // ring slot size in halves

// ================= MEGAFUSE: LN + 1x1 GEMM + dwconv3x3 + sumsq =================
// grid (3 paths, 16 strips, Bsz), 512 threads.
__global__ __launch_bounds__(512)
void megafuse(const float* __restrict__ cur, const float* __restrict__ pre,
              const float* __restrict__ ln1w, const float* __restrict__ ln1b,
              const float* __restrict__ ln2w, const float* __restrict__ ln2b,
              const float* __restrict__ qw1, const float* __restrict__ kvw1,
              const float* __restrict__ qb1, const float* __restrict__ kvb1,
              const float* __restrict__ qw2, const float* __restrict__ qb2,
              const float* __restrict__ kvw2, const float* __restrict__ kvb2)
{
    extern __shared__ bf16 sm[];
    bf16* As   = sm;                    // [128][SROW]
    bf16* Ws   = sm + 128 * SROW;       // [128][SROW]
    bf16* ring = sm + 2 * 128 * SROW;   // 3 x [128][RROW]
    __shared__ float2 red2[512];

    int tid = threadIdx.x, lane = tid & 31, w = tid >> 5;
    int path = blockIdx.x, strip = blockIdx.y, b = blockIdx.z;
    int y0 = strip * 8;

    const float* Ain; const float* lnw; const float* lnb; const float* Wf;
    const float* gb; const float* cwt; const float* cb;
    bf16* outp; int ldout, coloff, which, dosq;
    if (path == 0) {
        Ain = cur; lnw = ln2w; lnb = ln2b; Wf = qw1;
        gb = qb1; cwt = qw2; cb = qb2;
        outp = g_q2; ldout = 128; coloff = 0; which = 0; dosq = 1;
    } else if (path == 1) {
        Ain = pre; lnw = ln1w; lnb = ln1b; Wf = kvw1;
        gb = kvb1; cwt = kvw2; cb = kvb2;
        outp = g_kv2; ldout = 256; coloff = 0; which = 1; dosq = 1;
    } else {
        Ain = pre; lnw = ln1w; lnb = ln1b; Wf = kvw1 + 128 * 128;
        gb = kvb1 + 128; cwt = kvw2 + 128 * 9; cb = kvb2 + 128;
        outp = g_kv2; ldout = 256; coloff = 128; which = 0; dosq = 0;
    }

    for (int it = tid; it < 128 * 16; it += 512) {
        int o = it >> 4, c8 = (it & 15) * 8;
        const float* wp = Wf + (size_t)o * 128 + c8;
        float4 f0 = *(const float4*)wp;
        float4 f1 = *(const float4*)(wp + 4);
        bf16* dp = Ws + o * SROW + c8;
        *(__nv_bfloat162*)(dp)     = __floats2bfloat162_rn(f0.x, f0.y);
        *(__nv_bfloat162*)(dp + 2) = __floats2bfloat162_rn(f0.z, f0.w);
        *(__nv_bfloat162*)(dp + 4) = __floats2bfloat162_rn(f1.x, f1.y);
        *(__nv_bfloat162*)(dp + 6) = __floats2bfloat162_rn(f1.z, f1.w);
    }

    int cp = tid & 63, xg = tid >> 6;
    int cg = cp * 2;
    __nv_bfloat162 cw[9];
    #pragma unroll
    for (int t = 0; t < 9; t++)
        cw[t] = __floats2bfloat162_rn(cwt[cg * 9 + t], cwt[cg * 9 + 9 + t]);
    __nv_bfloat162 cb2 = __floats2bfloat162_rn(cb[cg], cb[cg + 1]);
    const __nv_bfloat162 zz = __floats2bfloat162_rn(0.f, 0.f);

    float4 wv = *(const float4*)(lnw + lane * 4);
    float4 bv = *(const float4*)(lnb + lane * 4);

    int wm = (w & 3) * 32, wn = (w >> 2) * 32;
    int arow  = (lane & 7) + ((lane >> 3) & 1) * 8;
    int akoff = (lane >> 4) * 8;
    int brow  = (lane & 7);
    int bkoff = ((lane >> 3) & 1) * 8;
    int g = lane >> 2, t2 = (lane & 3) * 2;

    float sq0 = 0.f, sq1 = 0.f;

    // prefetch first TWO rows into L2 (deeper startup pipeline)
    #pragma unroll
    for (int pr = 0; pr < 2; pr++) {
        int r = y0 - 1 + pr;
        if ((unsigned)r < 128u) {
            #pragma unroll
            for (int i = 0; i < 8; i++) {
                int p = w * 8 + i;
                pf_l2(Ain + ((size_t)b * HWsz + (size_t)r * 128 + p) * 128 + lane * 4);
            }
        }
    }

    for (int ri = 0; ri < 10; ri++) {
        int r = y0 - 1 + ri;
        bf16* rs = ring + (ri % 3) * SLOTH;

        if ((unsigned)r < 128u) {
            #pragma unroll
            for (int i = 0; i < 8; i++) {
                int p = w * 8 + i;
                const float* ap = Ain + ((size_t)b * HWsz + (size_t)r * 128 + p) * 128 + lane * 4;
                float4 v = *(const float4*)ap;
                float s  = v.x + v.y + v.z + v.w;
                float ss = fmaf(v.x, v.x, fmaf(v.y, v.y, fmaf(v.z, v.z, v.w * v.w)));
                #pragma unroll
                for (int o = 16; o; o >>= 1) {
                    s  += __shfl_xor_sync(0xFFFFFFFFu, s,  o);
                    ss += __shfl_xor_sync(0xFFFFFFFFu, ss, o);
                }
                float mu  = s * (1.0f / 128.0f);
                float inv = rsqrtf(ss * (1.0f / 128.0f) - mu * mu + 1e-5f);
                float x0 = (v.x - mu) * inv * wv.x + bv.x;
                float x1 = (v.y - mu) * inv * wv.y + bv.y;
                float x2 = (v.z - mu) * inv * wv.z + bv.z;
                float x3 = (v.w - mu) * inv * wv.w + bv.w;
                *(__nv_bfloat162*)(As + p * SROW + lane * 4)     = __floats2bfloat162_rn(x0, x1);
                *(__nv_bfloat162*)(As + p * SROW + lane * 4 + 2) = __floats2bfloat162_rn(x2, x3);
            }
            __syncthreads();

            {
                int rn = r + 2;
                if (ri + 2 < 10 && (unsigned)rn < 128u) {
                    #pragma unroll
                    for (int i = 0; i < 8; i++) {
                        int p = w * 8 + i;
                        pf_l2(Ain + ((size_t)b * HWsz + (size_t)rn * 128 + p) * 128 + lane * 4);
                    }
                }
            }

            float acc[2][4][4];
            #pragma unroll
            for (int mi = 0; mi < 2; mi++)
                #pragma unroll
                for (int ni = 0; ni < 4; ni++)
                    #pragma unroll
                    for (int t = 0; t < 4; t++) acc[mi][ni][t] = 0.f;

            #pragma unroll
            for (int k0 = 0; k0 < 128; k0 += 16) {
                unsigned af[2][4];
                unsigned bfr[4][2];
                #pragma unroll
                for (int mi = 0; mi < 2; mi++)
                    ldm_x4(af[mi], sptr(As + (wm + 16 * mi + arow) * SROW + k0 + akoff));
                #pragma unroll
                for (int ni = 0; ni < 4; ni++)
                    ldm_x2(bfr[ni], sptr(Ws + (wn + 8 * ni + brow) * SROW + k0 + bkoff));
                #pragma unroll
                for (int mi = 0; mi < 2; mi++)
                    #pragma unroll
                    for (int ni = 0; ni < 4; ni++)
                        mma16816(acc[mi][ni], af[mi], bfr[ni]);
            }

            #pragma unroll
            for (int mi = 0; mi < 2; mi++) {
                int p0 = wm + 16 * mi + g;
                #pragma unroll
                for (int ni = 0; ni < 4; ni++) {
                    int col = wn + 8 * ni + t2;
                    float2 bb = *(const float2*)(gb + col);
                    *(__nv_bfloat162*)(rs + p0 * RROW + col) =
                        __floats2bfloat162_rn(acc[mi][ni][0] + bb.x, acc[mi][ni][1] + bb.y);
                    *(__nv_bfloat162*)(rs + (p0 + 8) * RROW + col) =
                        __floats2bfloat162_rn(acc[mi][ni][2] + bb.x, acc[mi][ni][3] + bb.y);
                }
            }
            __syncthreads();
        } else {
            __syncthreads();
            for (int it = tid; it < 128 * (RROW / 2); it += 512)
                ((unsigned*)rs)[it] = 0u;
            __syncthreads();
        }

        if (ri >= 2) {
            const __nv_bfloat162* r0 = (const __nv_bfloat162*)(ring + ((ri - 2) % 3) * SLOTH);
            const __nv_bfloat162* r1 = (const __nv_bfloat162*)(ring + ((ri - 1) % 3) * SLOTH);
            const __nv_bfloat162* r2 = (const __nv_bfloat162*)(ring + (ri % 3) * SLOTH);
            int yo = y0 + ri - 2;
            int x0 = xg * 16;
            const int RW = RROW / 2;

            __nv_bfloat162 m0, m1, m2, c0, c1, c2;
            if (x0 > 0) {
                m0 = r0[(x0 - 1) * RW + cp]; m1 = r1[(x0 - 1) * RW + cp]; m2 = r2[(x0 - 1) * RW + cp];
            } else { m0 = zz; m1 = zz; m2 = zz; }
            c0 = r0[x0 * RW + cp]; c1 = r1[x0 * RW + cp]; c2 = r2[x0 * RW + cp];

            bf16* ob = outp + ((size_t)b * HWsz + (size_t)yo * 128) * ldout + coloff + cg;
            #pragma unroll 4
            for (int xi = 0; xi < 16; xi++) {
                int x = x0 + xi;
                __nv_bfloat162 p0, p1, p2;
                if (x < 127) {
                    p0 = r0[(x + 1) * RW + cp]; p1 = r1[(x + 1) * RW + cp]; p2 = r2[(x + 1) * RW + cp];
                } else { p0 = zz; p1 = zz; p2 = zz; }
                __nv_bfloat162 a = cb2;
                a = __hfma2(m0, cw[0], a); a = __hfma2(c0, cw[1], a); a = __hfma2(p0, cw[2], a);
                a = __hfma2(m1, cw[3], a); a = __hfma2(c1, cw[4], a); a = __hfma2(p1, cw[5], a);
                a = __hfma2(m2, cw[6], a); a = __hfma2(c2, cw[7], a); a = __hfma2(p2, cw[8], a);
                *(__nv_bfloat162*)(ob + (size_t)x * ldout) = a;
                if (dosq) {
                    float f0 = __bfloat162float(__low2bfloat16(a));
                    float f1 = __bfloat162float(__high2bfloat16(a));
                    sq0 = fmaf(f0, f0, sq0);
                    sq1 = fmaf(f1, f1, sq1);
                }
                m0 = c0; c0 = p0; m1 = c1; c1 = p1; m2 = c2; c2 = p2;
            }
        }
    }

    red2[tid] = make_float2(sq0, sq1);
    __syncthreads();
    if (dosq && tid < 64) {
        float t0 = 0.f, t1 = 0.f;
        #pragma unroll
        for (int xx = 0; xx < 8; xx++) {
            float2 v = red2[xx * 64 + tid];
            t0 += v.x; t1 += v.y;
        }
        float* dst = g_norm_part + ((size_t)(which * 8 + b) * 16 + strip) * 128 + tid * 2;
        dst[0] = t0; dst[1] = t1;
    }
}

// ---------------- QK^T: cp.async double-buffered pipeline ----------------
__global__ __launch_bounds__(256, 2)
void qk_kernel()
{
    __shared__ bf16 Qs[2][32 * SROW];
    __shared__ bf16 Ks[2][32 * SROW];
    int bx = blockIdx.x;
    int b = bx >> 5, chunk = bx & 31;
    const bf16* Qb = g_q2  + (size_t)b * HWsz * 128;
    const bf16* Kb = g_kv2 + (size_t)b * HWsz * 256;
    int tid = threadIdx.x, lane = tid & 31, w = tid >> 5;
    int wm = (w & 1) * 64, wn = (w >> 1) * 32;

    int at_row  = (lane & 7) + ((lane >> 4) & 1) * 8;
    int at_coff = ((lane >> 3) & 1) * 8;
    int bt_row  = (lane & 7) + ((lane >> 3) & 1) * 8;
    int g = lane >> 2, t2 = (lane & 3) * 2;

    int r0s = tid >> 4,         c0s = (tid & 15) * 8;
    int r1s = (tid + 256) >> 4, c1s = ((tid + 256) & 15) * 8;

    float acc[4][4][4];
    #pragma unroll
    for (int mi = 0; mi < 4; mi++)
        #pragma unroll
        for (int ni = 0; ni < 4; ni++)
            #pragma unroll
            for (int t = 0; t < 4; t++) acc[mi][ni][t] = 0.f;

    const int NS = 16;
    int nbase = chunk * 512;

    cp_async16(sptr(&Qs[0][r0s * SROW + c0s]), Qb + (size_t)(nbase + r0s) * 128 + c0s);
    cp_async16(sptr(&Qs[0][r1s * SROW + c1s]), Qb + (size_t)(nbase + r1s) * 128 + c1s);
    cp_async16(sptr(&Ks[0][r0s * SROW + c0s]), Kb + (size_t)(nbase + r0s) * 256 + c0s);
    cp_async16(sptr(&Ks[0][r1s * SROW + c1s]), Kb + (size_t)(nbase + r1s) * 256 + c1s);
    CP_COMMIT();

    for (int st = 0; st < NS; st++) {
        CP_WAIT0();
        __syncthreads();

        if (st + 1 < NS) {
            int n0 = nbase + (st + 1) * 32;
            int bb = (st + 1) & 1;
            cp_async16(sptr(&Qs[bb][r0s * SROW + c0s]), Qb + (size_t)(n0 + r0s) * 128 + c0s);
            cp_async16(sptr(&Qs[bb][r1s * SROW + c1s]), Qb + (size_t)(n0 + r1s) * 128 + c1s);
            cp_async16(sptr(&Ks[bb][r0s * SROW + c0s]), Kb + (size_t)(n0 + r0s) * 256 + c0s);
            cp_async16(sptr(&Ks[bb][r1s * SROW + c1s]), Kb + (size_t)(n0 + r1s) * 256 + c1s);
            CP_COMMIT();
        }

        const bf16* Qc = Qs[st & 1];
        const bf16* Kc = Ks[st & 1];
        #pragma unroll
        for (int k0 = 0; k0 < 32; k0 += 16) {
            unsigned af[4][4];
            unsigned bfr[4][2];
            #pragma unroll
            for (int mi = 0; mi < 4; mi++)
                ldm_x4_t(af[mi], sptr(Qc + (k0 + at_row) * SROW + wm + 16 * mi + at_coff));
            #pragma unroll
            for (int ni = 0; ni < 4; ni++)
                ldm_x2_t(bfr[ni], sptr(Kc + (k0 + bt_row) * SROW + wn + 8 * ni));
            #pragma unroll
            for (int mi = 0; mi < 4; mi++)
                #pragma unroll
                for (int ni = 0; ni < 4; ni++)
                    mma16816(acc[mi][ni], af[mi], bfr[ni]);
        }
    }

    float* P = g_att_part + (size_t)bx * 16384;
    #pragma unroll
    for (int mi = 0; mi < 4; mi++) {
        int row = wm + 16 * mi + g;
        #pragma unroll
        for (int ni = 0; ni < 4; ni++) {
            int col = wn + 8 * ni + t2;
            *(float2*)(P + row * 128 + col)       = make_float2(acc[mi][ni][0], acc[mi][ni][1]);
            *(float2*)(P + (row + 8) * 128 + col) = make_float2(acc[mi][ni][2], acc[mi][ni][3]);
        }
    }
}

// ---------------- softmax: one block per (b,c), thread = d ----------------
__global__ __launch_bounds__(128)
void softmax_kernel()
{
    __shared__ float rbuf[8];
    int bc = blockIdx.x;
    int b = bc >> 7, c = bc & 127;
    int d = threadIdx.x;

    float sq = 0.f, sk = 0.f;
    #pragma unroll
    for (int t = 0; t < 16; t++) {
        sq += g_norm_part[((size_t)b * 16 + t) * 128 + c];
        sk += g_norm_part[((size_t)(8 + b) * 16 + t) * 128 + d];
    }
    float invq = 1.0f / fmaxf(sqrtf(sq), 1e-12f);
    float invk = 1.0f / fmaxf(sqrtf(sk), 1e-12f);

    const float* P = g_att_part + ((size_t)b * NCHUNK * 128 + c) * 128 + d;
    float s = 0.f;
    #pragma unroll 8
    for (int ch = 0; ch < NCHUNK; ch++)
        s += P[(size_t)ch * 16384];

    float l = s * invq * invk;

    float mx = l;
    #pragma unroll
    for (int o = 16; o; o >>= 1) mx = fmaxf(mx, __shfl_xor_sync(0xFFFFFFFFu, mx, o));
    if ((d & 31) == 0) rbuf[d >> 5] = mx;
    __syncthreads();
    mx = fmaxf(fmaxf(rbuf[0], rbuf[1]), fmaxf(rbuf[2], rbuf[3]));

    float e = expf(l - mx);
    float sum = e;
    #pragma unroll
    for (int o = 16; o; o >>= 1) sum += __shfl_xor_sync(0xFFFFFFFFu, sum, o);
    __syncthreads();
    if ((d & 31) == 0) rbuf[4 + (d >> 5)] = sum;
    __syncthreads();
    sum = (rbuf[4] + rbuf[5]) + (rbuf[6] + rbuf[7]);

    g_att[(size_t)bc * 128 + d] = e / sum;
}

// ---------------- W2[b] = out_w @ att[b]: grid (Bsz, 16), 1024 thr, 8-way e-split ----------------
__global__ __launch_bounds__(1024)
void w2_kernel(const float* __restrict__ out_w)
{
    __shared__ float sw[8 * 128];
    __shared__ float red[8 * 8 * 128];
    int b = blockIdx.x, ct = blockIdx.y;
    int tid = threadIdx.x;
    int d = tid & 127, eh = tid >> 7;

    for (int it = tid; it < 8 * 128; it += 1024)
        sw[it] = out_w[(size_t)(ct * 8 + (it >> 7)) * 128 + (it & 127)];
    __syncthreads();

    float acc[8];
    #pragma unroll
    for (int ci = 0; ci < 8; ci++) acc[ci] = 0.f;

    const float* A = g_att + (size_t)b * 16384 + d;
    int e0 = eh * 16;
    #pragma unroll 8
    for (int ei = 0; ei < 16; ei++) {
        int e = e0 + ei;
        float a = A[(size_t)e * 128];
        #pragma unroll
        for (int ci = 0; ci < 8; ci++)
            acc[ci] = fmaf(sw[ci * 128 + e], a, acc[ci]);
    }

    #pragma unroll
    for (int ci = 0; ci < 8; ci++)
        red[(eh * 8 + ci) * 128 + d] = acc[ci];
    __syncthreads();

    {
        int idx = tid;
        int ci = idx >> 7, d2 = idx & 127;
        float v = 0.f;
        #pragma unroll
        for (int e8 = 0; e8 < 8; e8++)
            v += red[(e8 * 8 + ci) * 128 + d2];
        g_W2h[(size_t)b * 16384 + (size_t)(ct * 8 + ci) * 128 + d2] = __float2bfloat16_rn(v);
    }
}

// ---------------- final: out[b,n,c] = sum_d W2[c,d] v[b,n,d] + out_b[c] + cur ----------------
__global__ __launch_bounds__(256, 2)
void vgemm(const float* __restrict__ cur, const float* __restrict__ out_b,
           float* __restrict__ out)
{
    extern __shared__ bf16 sm[];
    bf16* As = sm;
    bf16* Bs = sm + 128 * SROW;
    int b = blockIdx.z;
    int m0 = blockIdx.y * 128;
    const bf16* V  = g_kv2 + (size_t)b * HWsz * 256 + 128;
    const bf16* W2 = g_W2h + (size_t)b * 16384;
    int tid = threadIdx.x, lane = tid & 31, w = tid >> 5;

    for (int it = tid; it < 128 * 16; it += 256) {
        int r = it >> 4, c8 = (it & 15) * 8;
        *(uint4*)(As + r * SROW + c8) = *(const uint4*)(V + (size_t)(m0 + r) * 256 + c8);
        *(uint4*)(Bs + r * SROW + c8) = *(const uint4*)(W2 + (size_t)r * 128 + c8);
    }
    __syncthreads();

    int wm = (w & 1) * 64, wn = (w >> 1) * 32;
    int arow  = (lane & 7) + ((lane >> 3) & 1) * 8;
    int akoff = (lane >> 4) * 8;
    int brow  = (lane & 7);
    int bkoff = ((lane >> 3) & 1) * 8;
    int g = lane >> 2, t2 = (lane & 3) * 2;

    float acc[4][4][4];
    #pragma unroll
    for (int mi = 0; mi < 4; mi++)
        #pragma unroll
        for (int ni = 0; ni < 4; ni++)
            #pragma unroll
            for (int t = 0; t < 4; t++) acc[mi][ni][t] = 0.f;

    for (int k0 = 0; k0 < 128; k0 += 16) {
        unsigned af[4][4];
        unsigned bfr[4][2];
        #pragma unroll
        for (int mi = 0; mi < 4; mi++)
            ldm_x4(af[mi], sptr(As + (wm + 16 * mi + arow) * SROW + k0 + akoff));
        #pragma unroll
        for (int ni = 0; ni < 4; ni++)
            ldm_x2(bfr[ni], sptr(Bs + (wn + 8 * ni + brow) * SROW + k0 + bkoff));
        #pragma unroll
        for (int mi = 0; mi < 4; mi++)
            #pragma unroll
            for (int ni = 0; ni < 4; ni++)
                mma16816(acc[mi][ni], af[mi], bfr[ni]);
    }

    const float* curb = cur + (size_t)b * HWsz * 128;
    float* outb = out + (size_t)b * HWsz * 128;
    #pragma unroll
    for (int mi = 0; mi < 4; mi++) {
        int r0 = m0 + wm + 16 * mi + g;
        #pragma unroll
        for (int ni = 0; ni < 4; ni++) {
            int col = wn + 8 * ni + t2;
            float2 bb = *(const float2*)(out_b + col);
            float2 c0 = *(const float2*)(curb + (size_t)r0 * 128 + col);
            float2 c1 = *(const float2*)(curb + (size_t)(r0 + 8) * 128 + col);
            *(float2*)(outb + (size_t)r0 * 128 + col) =
                make_float2(acc[mi][ni][0] + bb.x + c0.x, acc[mi][ni][1] + bb.y + c0.y);
            *(float2*)(outb + (size_t)(r0 + 8) * 128 + col) =
                make_float2(acc[mi][ni][2] + bb.x + c1.x, acc[mi][ni][3] + bb.y + c1.y);
        }
    }
}

// ---------------- host ----------------
extern "C" void kernel_launch(void* const* d_in, const int* in_sizes, int n_in,
                              void* d_out, int out_size)
{
    const float* pre   = (const float*)d_in[0];
    const float* cur   = (const float*)d_in[1];
    const float* ln1_w = (const float*)d_in[2];
    const float* ln1_b = (const float*)d_in[3];
    const float* ln2_w = (const float*)d_in[4];
    const float* ln2_b = (const float*)d_in[5];
    const float* q_w1  = (const float*)d_in[6];
    const float* q_b1  = (const float*)d_in[7];
    const float* q_w2  = (const float*)d_in[8];
    const float* q_b2  = (const float*)d_in[9];
    const float* kv_w1 = (const float*)d_in[10];
    const float* kv_b1 = (const float*)d_in[11];
    const float* kv_w2 = (const float*)d_in[12];
    const float* kv_b2 = (const float*)d_in[13];
    const float* out_w = (const float*)d_in[14];
    const float* out_b = (const float*)d_in[15];
    float* out = (float*)d_out;

    const int SMEM_GEMM = 2 * 128 * SROW * (int)sizeof(bf16);                // 69632
    const int SMEM_MF   = (2 * 128 * SROW + 3 * SLOTH) * (int)sizeof(bf16);  // 171008
    cudaFuncSetAttribute(megafuse, cudaFuncAttributeMaxDynamicSharedMemorySize, SMEM_MF);
    cudaFuncSetAttribute(vgemm,    cudaFuncAttributeMaxDynamicSharedMemorySize, SMEM_GEMM);

    megafuse<<<dim3(3, 16, Bsz), 512, SMEM_MF>>>(cur, pre, ln1_w, ln1_b, ln2_w, ln2_b,
                                                 q_w1, kv_w1, q_b1, kv_b1,
                                                 q_w2, q_b2, kv_w2, kv_b2);

    qk_kernel<<<Bsz * NCHUNK, 256>>>();

    softmax_kernel<<<Bsz * 128, 128>>>();

    w2_kernel<<<dim3(Bsz, 16), 1024>>>(out_w);

    vgemm<<<dim3(1, HWsz / 128, Bsz), 256, SMEM_GEMM>>>(cur, out_b, out);

    (void)in_sizes; (void)n_in; (void)out_size;
}

// round 17
// speedup vs baseline: 1.0266x; 1.0054x over previous
#include <cuda_runtime.h>
#include <cuda_bf16.h>
#include <cstdint>
#include <cstring>
#include <math.h>

#define Bsz 8
#define HWsz 16384
#define Cch 128
#define Ntot (Bsz*HWsz)
#define NCHUNK 32         // qk split-K chunks per batch
typedef __nv_bfloat16 bf16;

// ---------------- scratch (device globals; no allocation) ----------------
__device__ bf16  g_q2[(size_t)Ntot*Cch];
__device__ bf16  g_kv2[(size_t)Ntot*2*Cch];
__device__ float g_att_part[(size_t)Bsz*NCHUNK*Cch*Cch];
__device__ float g_att[(size_t)Bsz*Cch*Cch];
__device__ float g_norm_part[2*Bsz*16*Cch];
__device__ bf16  g_W2h[Bsz*Cch*Cch];

// ---------------- mma / ldmatrix / cp.async helpers ----------------
__device__ __forceinline__ unsigned sptr(const void* p) {
    return (unsigned)__cvta_generic_to_shared(p);
}
__device__ __forceinline__ void ldm_x4(unsigned* r, unsigned a) {
    asm volatile("ldmatrix.sync.aligned.m8n8.x4.shared.b16 {%0,%1,%2,%3}, [%4];"
        : "=r"(r[0]), "=r"(r[1]), "=r"(r[2]), "=r"(r[3]) : "r"(a));
}
__device__ __forceinline__ void ldm_x4_t(unsigned* r, unsigned a) {
    asm volatile("ldmatrix.sync.aligned.m8n8.x4.trans.shared.b16 {%0,%1,%2,%3}, [%4];"
        : "=r"(r[0]), "=r"(r[1]), "=r"(r[2]), "=r"(r[3]) : "r"(a));
}
__device__ __forceinline__ void ldm_x2(unsigned* r, unsigned a) {
    asm volatile("ldmatrix.sync.aligned.m8n8.x2.shared.b16 {%0,%1}, [%2];"
        : "=r"(r[0]), "=r"(r[1]) : "r"(a));
}
__device__ __forceinline__ void ldm_x2_t(unsigned* r, unsigned a) {
    asm volatile("ldmatrix.sync.aligned.m8n8.x2.trans.shared.b16 {%0,%1}, [%2];"
        : "=r"(r[0]), "=r"(r[1]) : "r"(a));
}
__device__ __forceinline__ void mma16816(float* c, const unsigned* a, const unsigned* b) {
    asm volatile("mma.sync.aligned.m16n8k16.row.col.f32.bf16.bf16.f32 "
        "{%0,%1,%2,%3},{%4,%5,%6,%7},{%8,%9},{%0,%1,%2,%3};"
        : "+f"(c[0]), "+f"(c[1]), "+f"(c[2]), "+f"(c[3])
        : "r"(a[0]), "r"(a[1]), "r"(a[2]), "r"(a[3]), "r"(b[0]), "r"(b[1]));
}
__device__ __forceinline__ void pf_l2(const void* p) {
    asm volatile("prefetch.global.L2 [%0];" :: "l"(p));
}
__device__ __forceinline__ void cp_async16(unsigned dst, const void* src) {
    asm volatile("cp.async.cg.shared.global [%0], [%1], 16;" :: "r"(dst), "l"(src));
}
#define CP_COMMIT() asm volatile("cp.async.commit_group;" ::: "memory")
#define CP_WAIT0()  asm volatile("cp.async.wait_group 0;" ::: "memory")

#define SROW 136          // ldmatrix-padded stride (halves)
#define RROW 132          // ring row stride (halves)
#define SLOTH (128*RROW)  // ring slot size in halves

// ================= MEGAFUSE: LN + 1x1 GEMM + dwconv3x3 + sumsq =================
// grid (3 paths, 16 strips, Bsz), 512 threads.
__global__ __launch_bounds__(512)
void megafuse(const float* __restrict__ cur, const float* __restrict__ pre,
              const float* __restrict__ ln1w, const float* __restrict__ ln1b,
              const float* __restrict__ ln2w, const float* __restrict__ ln2b,
              const float* __restrict__ qw1, const float* __restrict__ kvw1,
              const float* __restrict__ qb1, const float* __restrict__ kvb1,
              const float* __restrict__ qw2, const float* __restrict__ qb2,
              const float* __restrict__ kvw2, const float* __restrict__ kvb2)
{
    extern __shared__ bf16 sm[];
    bf16* As   = sm;                    // [128][SROW]
    bf16* Ws   = sm + 128 * SROW;       // [128][SROW]
    bf16* ring = sm + 2 * 128 * SROW;   // 3 x [128][RROW]
    __shared__ float2 red2[512];

    int tid = threadIdx.x, lane = tid & 31, w = tid >> 5;
    int path = blockIdx.x, strip = blockIdx.y, b = blockIdx.z;
    int y0 = strip * 8;

    const float* Ain; const float* lnw; const float* lnb; const float* Wf;
    const float* gb; const float* cwt; const float* cb;
    bf16* outp; int ldout, coloff, which, dosq;
    if (path == 0) {
        Ain = cur; lnw = ln2w; lnb = ln2b; Wf = qw1;
        gb = qb1; cwt = qw2; cb = qb2;
        outp = g_q2; ldout = 128; coloff = 0; which = 0; dosq = 1;
    } else if (path == 1) {
        Ain = pre; lnw = ln1w; lnb = ln1b; Wf = kvw1;
        gb = kvb1; cwt = kvw2; cb = kvb2;
        outp = g_kv2; ldout = 256; coloff = 0; which = 1; dosq = 1;
    } else {
        Ain = pre; lnw = ln1w; lnb = ln1b; Wf = kvw1 + 128 * 128;
        gb = kvb1 + 128; cwt = kvw2 + 128 * 9; cb = kvb2 + 128;
        outp = g_kv2; ldout = 256; coloff = 128; which = 0; dosq = 0;
    }

    for (int it = tid; it < 128 * 16; it += 512) {
        int o = it >> 4, c8 = (it & 15) * 8;
        const float* wp = Wf + (size_t)o * 128 + c8;
        float4 f0 = *(const float4*)wp;
        float4 f1 = *(const float4*)(wp + 4);
        bf16* dp = Ws + o * SROW + c8;
        *(__nv_bfloat162*)(dp)     = __floats2bfloat162_rn(f0.x, f0.y);
        *(__nv_bfloat162*)(dp + 2) = __floats2bfloat162_rn(f0.z, f0.w);
        *(__nv_bfloat162*)(dp + 4) = __floats2bfloat162_rn(f1.x, f1.y);
        *(__nv_bfloat162*)(dp + 6) = __floats2bfloat162_rn(f1.z, f1.w);
    }

    int cp = tid & 63, xg = tid >> 6;
    int cg = cp * 2;
    __nv_bfloat162 cw[9];
    #pragma unroll
    for (int t = 0; t < 9; t++)
        cw[t] = __floats2bfloat162_rn(cwt[cg * 9 + t], cwt[cg * 9 + 9 + t]);
    __nv_bfloat162 cb2 = __floats2bfloat162_rn(cb[cg], cb[cg + 1]);
    const __nv_bfloat162 zz = __floats2bfloat162_rn(0.f, 0.f);

    float4 wv = *(const float4*)(lnw + lane * 4);
    float4 bv = *(const float4*)(lnb + lane * 4);

    int wm = (w & 3) * 32, wn = (w >> 2) * 32;
    int arow  = (lane & 7) + ((lane >> 3) & 1) * 8;
    int akoff = (lane >> 4) * 8;
    int brow  = (lane & 7);
    int bkoff = ((lane >> 3) & 1) * 8;
    int g = lane >> 2, t2 = (lane & 3) * 2;

    float sq0 = 0.f, sq1 = 0.f;

    {
        int r = y0 - 1;
        if ((unsigned)r < 128u) {
            #pragma unroll
            for (int i = 0; i < 8; i++) {
                int p = w * 8 + i;
                pf_l2(Ain + ((size_t)b * HWsz + (size_t)r * 128 + p) * 128 + lane * 4);
            }
        }
    }

    for (int ri = 0; ri < 10; ri++) {
        int r = y0 - 1 + ri;
        bf16* rs = ring + (ri % 3) * SLOTH;

        if ((unsigned)r < 128u) {
            #pragma unroll
            for (int i = 0; i < 8; i++) {
                int p = w * 8 + i;
                const float* ap = Ain + ((size_t)b * HWsz + (size_t)r * 128 + p) * 128 + lane * 4;
                float4 v = *(const float4*)ap;
                float s  = v.x + v.y + v.z + v.w;
                float ss = fmaf(v.x, v.x, fmaf(v.y, v.y, fmaf(v.z, v.z, v.w * v.w)));
                #pragma unroll
                for (int o = 16; o; o >>= 1) {
                    s  += __shfl_xor_sync(0xFFFFFFFFu, s,  o);
                    ss += __shfl_xor_sync(0xFFFFFFFFu, ss, o);
                }
                float mu  = s * (1.0f / 128.0f);
                float inv = rsqrtf(ss * (1.0f / 128.0f) - mu * mu + 1e-5f);
                float x0 = (v.x - mu) * inv * wv.x + bv.x;
                float x1 = (v.y - mu) * inv * wv.y + bv.y;
                float x2 = (v.z - mu) * inv * wv.z + bv.z;
                float x3 = (v.w - mu) * inv * wv.w + bv.w;
                *(__nv_bfloat162*)(As + p * SROW + lane * 4)     = __floats2bfloat162_rn(x0, x1);
                *(__nv_bfloat162*)(As + p * SROW + lane * 4 + 2) = __floats2bfloat162_rn(x2, x3);
            }
            __syncthreads();

            {
                int rn = r + 1;
                if (ri + 1 < 10 && (unsigned)rn < 128u) {
                    #pragma unroll
                    for (int i = 0; i < 8; i++) {
                        int p = w * 8 + i;
                        pf_l2(Ain + ((size_t)b * HWsz + (size_t)rn * 128 + p) * 128 + lane * 4);
                    }
                }
            }

            float acc[2][4][4];
            #pragma unroll
            for (int mi = 0; mi < 2; mi++)
                #pragma unroll
                for (int ni = 0; ni < 4; ni++)
                    #pragma unroll
                    for (int t = 0; t < 4; t++) acc[mi][ni][t] = 0.f;

            #pragma unroll
            for (int k0 = 0; k0 < 128; k0 += 16) {
                unsigned af[2][4];
                unsigned bfr[4][2];
                #pragma unroll
                for (int mi = 0; mi < 2; mi++)
                    ldm_x4(af[mi], sptr(As + (wm + 16 * mi + arow) * SROW + k0 + akoff));
                #pragma unroll
                for (int ni = 0; ni < 4; ni++)
                    ldm_x2(bfr[ni], sptr(Ws + (wn + 8 * ni + brow) * SROW + k0 + bkoff));
                #pragma unroll
                for (int mi = 0; mi < 2; mi++)
                    #pragma unroll
                    for (int ni = 0; ni < 4; ni++)
                        mma16816(acc[mi][ni], af[mi], bfr[ni]);
            }

            #pragma unroll
            for (int mi = 0; mi < 2; mi++) {
                int p0 = wm + 16 * mi + g;
                #pragma unroll
                for (int ni = 0; ni < 4; ni++) {
                    int col = wn + 8 * ni + t2;
                    float2 bb = *(const float2*)(gb + col);
                    *(__nv_bfloat162*)(rs + p0 * RROW + col) =
                        __floats2bfloat162_rn(acc[mi][ni][0] + bb.x, acc[mi][ni][1] + bb.y);
                    *(__nv_bfloat162*)(rs + (p0 + 8) * RROW + col) =
                        __floats2bfloat162_rn(acc[mi][ni][2] + bb.x, acc[mi][ni][3] + bb.y);
                }
            }
            __syncthreads();
        } else {
            __syncthreads();
            for (int it = tid; it < 128 * (RROW / 2); it += 512)
                ((unsigned*)rs)[it] = 0u;
            __syncthreads();
        }

        if (ri >= 2) {
            const __nv_bfloat162* r0 = (const __nv_bfloat162*)(ring + ((ri - 2) % 3) * SLOTH);
            const __nv_bfloat162* r1 = (const __nv_bfloat162*)(ring + ((ri - 1) % 3) * SLOTH);
            const __nv_bfloat162* r2 = (const __nv_bfloat162*)(ring + (ri % 3) * SLOTH);
            int yo = y0 + ri - 2;
            int x0 = xg * 16;
            const int RW = RROW / 2;

            __nv_bfloat162 m0, m1, m2, c0, c1, c2;
            if (x0 > 0) {
                m0 = r0[(x0 - 1) * RW + cp]; m1 = r1[(x0 - 1) * RW + cp]; m2 = r2[(x0 - 1) * RW + cp];
            } else { m0 = zz; m1 = zz; m2 = zz; }
            c0 = r0[x0 * RW + cp]; c1 = r1[x0 * RW + cp]; c2 = r2[x0 * RW + cp];

            bf16* ob = outp + ((size_t)b * HWsz + (size_t)yo * 128) * ldout + coloff + cg;
            #pragma unroll 4
            for (int xi = 0; xi < 16; xi++) {
                int x = x0 + xi;
                __nv_bfloat162 p0, p1, p2;
                if (x < 127) {
                    p0 = r0[(x + 1) * RW + cp]; p1 = r1[(x + 1) * RW + cp]; p2 = r2[(x + 1) * RW + cp];
                } else { p0 = zz; p1 = zz; p2 = zz; }
                __nv_bfloat162 a = cb2;
                a = __hfma2(m0, cw[0], a); a = __hfma2(c0, cw[1], a); a = __hfma2(p0, cw[2], a);
                a = __hfma2(m1, cw[3], a); a = __hfma2(c1, cw[4], a); a = __hfma2(p1, cw[5], a);
                a = __hfma2(m2, cw[6], a); a = __hfma2(c2, cw[7], a); a = __hfma2(p2, cw[8], a);
                *(__nv_bfloat162*)(ob + (size_t)x * ldout) = a;
                if (dosq) {
                    float f0 = __bfloat162float(__low2bfloat16(a));
                    float f1 = __bfloat162float(__high2bfloat16(a));
                    sq0 = fmaf(f0, f0, sq0);
                    sq1 = fmaf(f1, f1, sq1);
                }
                m0 = c0; c0 = p0; m1 = c1; c1 = p1; m2 = c2; c2 = p2;
            }
        }
    }

    red2[tid] = make_float2(sq0, sq1);
    __syncthreads();
    if (dosq && tid < 64) {
        float t0 = 0.f, t1 = 0.f;
        #pragma unroll
        for (int xx = 0; xx < 8; xx++) {
            float2 v = red2[xx * 64 + tid];
            t0 += v.x; t1 += v.y;
        }
        float* dst = g_norm_part + ((size_t)(which * 8 + b) * 16 + strip) * 128 + tid * 2;
        dst[0] = t0; dst[1] = t1;
    }
}

// ---------------- QK^T: cp.async double-buffered pipeline ----------------
__global__ __launch_bounds__(256, 2)
void qk_kernel()
{
    __shared__ bf16 Qs[2][32 * SROW];
    __shared__ bf16 Ks[2][32 * SROW];
    int bx = blockIdx.x;
    int b = bx >> 5, chunk = bx & 31;
    const bf16* Qb = g_q2  + (size_t)b * HWsz * 128;
    const bf16* Kb = g_kv2 + (size_t)b * HWsz * 256;
    int tid = threadIdx.x, lane = tid & 31, w = tid >> 5;
    int wm = (w & 1) * 64, wn = (w >> 1) * 32;

    int at_row  = (lane & 7) + ((lane >> 4) & 1) * 8;
    int at_coff = ((lane >> 3) & 1) * 8;
    int bt_row  = (lane & 7) + ((lane >> 3) & 1) * 8;
    int g = lane >> 2, t2 = (lane & 3) * 2;

    int r0s = tid >> 4,         c0s = (tid & 15) * 8;
    int r1s = (tid + 256) >> 4, c1s = ((tid + 256) & 15) * 8;

    float acc[4][4][4];
    #pragma unroll
    for (int mi = 0; mi < 4; mi++)
        #pragma unroll
        for (int ni = 0; ni < 4; ni++)
            #pragma unroll
            for (int t = 0; t < 4; t++) acc[mi][ni][t] = 0.f;

    const int NS = 16;
    int nbase = chunk * 512;

    cp_async16(sptr(&Qs[0][r0s * SROW + c0s]), Qb + (size_t)(nbase + r0s) * 128 + c0s);
    cp_async16(sptr(&Qs[0][r1s * SROW + c1s]), Qb + (size_t)(nbase + r1s) * 128 + c1s);
    cp_async16(sptr(&Ks[0][r0s * SROW + c0s]), Kb + (size_t)(nbase + r0s) * 256 + c0s);
    cp_async16(sptr(&Ks[0][r1s * SROW + c1s]), Kb + (size_t)(nbase + r1s) * 256 + c1s);
    CP_COMMIT();

    for (int st = 0; st < NS; st++) {
        CP_WAIT0();
        __syncthreads();

        if (st + 1 < NS) {
            int n0 = nbase + (st + 1) * 32;
            int bb = (st + 1) & 1;
            cp_async16(sptr(&Qs[bb][r0s * SROW + c0s]), Qb + (size_t)(n0 + r0s) * 128 + c0s);
            cp_async16(sptr(&Qs[bb][r1s * SROW + c1s]), Qb + (size_t)(n0 + r1s) * 128 + c1s);
            cp_async16(sptr(&Ks[bb][r0s * SROW + c0s]), Kb + (size_t)(n0 + r0s) * 256 + c0s);
            cp_async16(sptr(&Ks[bb][r1s * SROW + c1s]), Kb + (size_t)(n0 + r1s) * 256 + c1s);
            CP_COMMIT();
        }

        const bf16* Qc = Qs[st & 1];
        const bf16* Kc = Ks[st & 1];
        #pragma unroll
        for (int k0 = 0; k0 < 32; k0 += 16) {
            unsigned af[4][4];
            unsigned bfr[4][2];
            #pragma unroll
            for (int mi = 0; mi < 4; mi++)
                ldm_x4_t(af[mi], sptr(Qc + (k0 + at_row) * SROW + wm + 16 * mi + at_coff));
            #pragma unroll
            for (int ni = 0; ni < 4; ni++)
                ldm_x2_t(bfr[ni], sptr(Kc + (k0 + bt_row) * SROW + wn + 8 * ni));
            #pragma unroll
            for (int mi = 0; mi < 4; mi++)
                #pragma unroll
                for (int ni = 0; ni < 4; ni++)
                    mma16816(acc[mi][ni], af[mi], bfr[ni]);
        }
    }

    // streaming (evict-first) stores: partials are read exactly once by softmax
    float* P = g_att_part + (size_t)bx * 16384;
    #pragma unroll
    for (int mi = 0; mi < 4; mi++) {
        int row = wm + 16 * mi + g;
        #pragma unroll
        for (int ni = 0; ni < 4; ni++) {
            int col = wn + 8 * ni + t2;
            __stcs((float2*)(P + row * 128 + col),       make_float2(acc[mi][ni][0], acc[mi][ni][1]));
            __stcs((float2*)(P + (row + 8) * 128 + col), make_float2(acc[mi][ni][2], acc[mi][ni][3]));
        }
    }
}

// ---------------- softmax: one block per (b,c), thread = d ----------------
__global__ __launch_bounds__(128)
void softmax_kernel()
{
    __shared__ float rbuf[8];
    int bc = blockIdx.x;
    int b = bc >> 7, c = bc & 127;
    int d = threadIdx.x;

    float sq = 0.f, sk = 0.f;
    #pragma unroll
    for (int t = 0; t < 16; t++) {
        sq += g_norm_part[((size_t)b * 16 + t) * 128 + c];
        sk += g_norm_part[((size_t)(8 + b) * 16 + t) * 128 + d];
    }
    float invq = 1.0f / fmaxf(sqrtf(sq), 1e-12f);
    float invk = 1.0f / fmaxf(sqrtf(sk), 1e-12f);

    const float* P = g_att_part + ((size_t)b * NCHUNK * 128 + c) * 128 + d;
    float s = 0.f;
    #pragma unroll 8
    for (int ch = 0; ch < NCHUNK; ch++)
        s += __ldcs(P + (size_t)ch * 16384);   // streaming read (read-once data)

    float l = s * invq * invk;

    float mx = l;
    #pragma unroll
    for (int o = 16; o; o >>= 1) mx = fmaxf(mx, __shfl_xor_sync(0xFFFFFFFFu, mx, o));
    if ((d & 31) == 0) rbuf[d >> 5] = mx;
    __syncthreads();
    mx = fmaxf(fmaxf(rbuf[0], rbuf[1]), fmaxf(rbuf[2], rbuf[3]));

    float e = expf(l - mx);
    float sum = e;
    #pragma unroll
    for (int o = 16; o; o >>= 1) sum += __shfl_xor_sync(0xFFFFFFFFu, sum, o);
    __syncthreads();
    if ((d & 31) == 0) rbuf[4 + (d >> 5)] = sum;
    __syncthreads();
    sum = (rbuf[4] + rbuf[5]) + (rbuf[6] + rbuf[7]);

    g_att[(size_t)bc * 128 + d] = e / sum;
}

// ---------------- W2[b] = out_w @ att[b]: grid (Bsz, 16), 1024 thr, 8-way e-split ----------------
__global__ __launch_bounds__(1024)
void w2_kernel(const float* __restrict__ out_w)
{
    __shared__ float sw[8 * 128];
    __shared__ float red[8 * 8 * 128];
    int b = blockIdx.x, ct = blockIdx.y;
    int tid = threadIdx.x;
    int d = tid & 127, eh = tid >> 7;

    for (int it = tid; it < 8 * 128; it += 1024)
        sw[it] = out_w[(size_t)(ct * 8 + (it >> 7)) * 128 + (it & 127)];
    __syncthreads();

    float acc[8];
    #pragma unroll
    for (int ci = 0; ci < 8; ci++) acc[ci] = 0.f;

    const float* A = g_att + (size_t)b * 16384 + d;
    int e0 = eh * 16;
    #pragma unroll 8
    for (int ei = 0; ei < 16; ei++) {
        int e = e0 + ei;
        float a = A[(size_t)e * 128];
        #pragma unroll
        for (int ci = 0; ci < 8; ci++)
            acc[ci] = fmaf(sw[ci * 128 + e], a, acc[ci]);
    }

    #pragma unroll
    for (int ci = 0; ci < 8; ci++)
        red[(eh * 8 + ci) * 128 + d] = acc[ci];
    __syncthreads();

    {
        int idx = tid;
        int ci = idx >> 7, d2 = idx & 127;
        float v = 0.f;
        #pragma unroll
        for (int e8 = 0; e8 < 8; e8++)
            v += red[(e8 * 8 + ci) * 128 + d2];
        g_W2h[(size_t)b * 16384 + (size_t)(ct * 8 + ci) * 128 + d2] = __float2bfloat16_rn(v);
    }
}

// ---------------- final: out[b,n,c] = sum_d W2[c,d] v[b,n,d] + out_b[c] + cur ----------------
__global__ __launch_bounds__(256, 2)
void vgemm(const float* __restrict__ cur, const float* __restrict__ out_b,
           float* __restrict__ out)
{
    extern __shared__ bf16 sm[];
    bf16* As = sm;
    bf16* Bs = sm + 128 * SROW;
    int b = blockIdx.z;
    int m0 = blockIdx.y * 128;
    const bf16* V  = g_kv2 + (size_t)b * HWsz * 256 + 128;
    const bf16* W2 = g_W2h + (size_t)b * 16384;
    int tid = threadIdx.x, lane = tid & 31, w = tid >> 5;

    for (int it = tid; it < 128 * 16; it += 256) {
        int r = it >> 4, c8 = (it & 15) * 8;
        *(uint4*)(As + r * SROW + c8) = *(const uint4*)(V + (size_t)(m0 + r) * 256 + c8);
        *(uint4*)(Bs + r * SROW + c8) = *(const uint4*)(W2 + (size_t)r * 128 + c8);
    }
    __syncthreads();

    int wm = (w & 1) * 64, wn = (w >> 1) * 32;
    int arow  = (lane & 7) + ((lane >> 3) & 1) * 8;
    int akoff = (lane >> 4) * 8;
    int brow  = (lane & 7);
    int bkoff = ((lane >> 3) & 1) * 8;
    int g = lane >> 2, t2 = (lane & 3) * 2;

    float acc[4][4][4];
    #pragma unroll
    for (int mi = 0; mi < 4; mi++)
        #pragma unroll
        for (int ni = 0; ni < 4; ni++)
            #pragma unroll
            for (int t = 0; t < 4; t++) acc[mi][ni][t] = 0.f;

    for (int k0 = 0; k0 < 128; k0 += 16) {
        unsigned af[4][4];
        unsigned bfr[4][2];
        #pragma unroll
        for (int mi = 0; mi < 4; mi++)
            ldm_x4(af[mi], sptr(As + (wm + 16 * mi + arow) * SROW + k0 + akoff));
        #pragma unroll
        for (int ni = 0; ni < 4; ni++)
            ldm_x2(bfr[ni], sptr(Bs + (wn + 8 * ni + brow) * SROW + k0 + bkoff));
        #pragma unroll
        for (int mi = 0; mi < 4; mi++)
            #pragma unroll
            for (int ni = 0; ni < 4; ni++)
                mma16816(acc[mi][ni], af[mi], bfr[ni]);
    }

    const float* curb = cur + (size_t)b * HWsz * 128;
    float* outb = out + (size_t)b * HWsz * 128;
    #pragma unroll
    for (int mi = 0; mi < 4; mi++) {
        int r0 = m0 + wm + 16 * mi + g;
        #pragma unroll
        for (int ni = 0; ni < 4; ni++) {
            int col = wn + 8 * ni + t2;
            float2 bb = *(const float2*)(out_b + col);
            float2 c0 = *(const float2*)(curb + (size_t)r0 * 128 + col);
            float2 c1 = *(const float2*)(curb + (size_t)(r0 + 8) * 128 + col);
            *(float2*)(outb + (size_t)r0 * 128 + col) =
                make_float2(acc[mi][ni][0] + bb.x + c0.x, acc[mi][ni][1] + bb.y + c0.y);
            *(float2*)(outb + (size_t)(r0 + 8) * 128 + col) =
                make_float2(acc[mi][ni][2] + bb.x + c1.x, acc[mi][ni][3] + bb.y + c1.y);
        }
    }
}

// ---------------- host ----------------
extern "C" void kernel_launch(void* const* d_in, const int* in_sizes, int n_in,
                              void* d_out, int out_size)
{
    const float* pre   = (const float*)d_in[0];
    const float* cur   = (const float*)d_in[1];
    const float* ln1_w = (const float*)d_in[2];
    const float* ln1_b = (const float*)d_in[3];
    const float* ln2_w = (const float*)d_in[4];
    const float* ln2_b = (const float*)d_in[5];
    const float* q_w1  = (const float*)d_in[6];
    const float* q_b1  = (const float*)d_in[7];
    const float* q_w2  = (const float*)d_in[8];
    const float* q_b2  = (const float*)d_in[9];
    const float* kv_w1 = (const float*)d_in[10];
    const float* kv_b1 = (const float*)d_in[11];
    const float* kv_w2 = (const float*)d_in[12];
    const float* kv_b2 = (const float*)d_in[13];
    const float* out_w = (const float*)d_in[14];
    const float* out_b = (const float*)d_in[15];
    float* out = (float*)d_out;

    const int SMEM_GEMM = 2 * 128 * SROW * (int)sizeof(bf16);                // 69632
    const int SMEM_MF   = (2 * 128 * SROW + 3 * SLOTH) * (int)sizeof(bf16);  // 171008
    cudaFuncSetAttribute(megafuse, cudaFuncAttributeMaxDynamicSharedMemorySize, SMEM_MF);
    cudaFuncSetAttribute(vgemm,    cudaFuncAttributeMaxDynamicSharedMemorySize, SMEM_GEMM);

    megafuse<<<dim3(3, 16, Bsz), 512, SMEM_MF>>>(cur, pre, ln1_w, ln1_b, ln2_w, ln2_b,
                                                 q_w1, kv_w1, q_b1, kv_b1,
                                                 q_w2, q_b2, kv_w2, kv_b2);

    qk_kernel<<<Bsz * NCHUNK, 256>>>();

    softmax_kernel<<<Bsz * 128, 128>>>();

    w2_kernel<<<dim3(Bsz, 16), 1024>>>(out_w);

    vgemm<<<dim3(1, HWsz / 128, Bsz), 256, SMEM_GEMM>>>(cur, out_b, out);

    (void)in_sizes; (void)n_in; (void)out_size;
}